// round 8
// baseline (speedup 1.0000x reference)
#include <cuda_runtime.h>

#define T_STEPS 512
#define BATCH   64
#define HID     512
#define GATES3  1536
#define NB_REC  128
#define NT_REC  256
#define WR      516   // float stride for smem rows (padded: conflict-free)

// ---------------- scratch (static device allocations; no cudaMalloc) ----------------
__device__ float g_xg[(size_t)T_STEPS * BATCH * GATES3]; // precomputed input gates
__device__ float g_y0[(size_t)T_STEPS * BATCH * HID];    // layer-0 output
__device__ float g_hx[2 * BATCH * HID];                  // ping-pong h exchange [parity][b][j]
__device__ unsigned g_flags[NB_REC];                     // per-block step flags
__device__ unsigned g_end_cnt[8];
__device__ volatile unsigned g_end_gen[8];

// ---------------- packed fp32x2 FMA (Blackwell FFMA2) ----------------
__device__ __forceinline__ float2 ffma2(float2 a, float2 b, float2 c) {
    float2 d;
    asm("fma.rn.f32x2 %0, %1, %2, %3;"
        : "=l"(reinterpret_cast<unsigned long long&>(d))
        : "l"(reinterpret_cast<unsigned long long&>(a)),
          "l"(reinterpret_cast<unsigned long long&>(b)),
          "l"(reinterpret_cast<unsigned long long&>(c)));
    return d;
}

__device__ __forceinline__ float fast_sigmoid(float x) {
    return __fdividef(1.f, 1.f + __expf(-x));
}
__device__ __forceinline__ float fast_tanh(float x) {
    float r;
    asm("tanh.approx.f32 %0, %1;" : "=f"(r) : "f"(x));
    return r;
}

// ---------------- GEMM: out[M,N] = A[M,K] * W[N,K]^T + bias (R2 body, 2 blocks/SM) ----
__global__ void __launch_bounds__(256, 2) gemm_bias_kernel(
    const float* __restrict__ A, const float* __restrict__ W,
    const float* __restrict__ bias, float* __restrict__ out, int K)
{
    __shared__ float As[16 * 132];
    __shared__ float Bs[16 * 132];

    const int tid = threadIdx.x;
    const int m0 = blockIdx.y * 128;
    const int n0 = blockIdx.x * 128;
    const int tm = tid >> 4;
    const int tn = tid & 15;

    float2 c2[8][4];
#pragma unroll
    for (int i = 0; i < 8; ++i)
#pragma unroll
        for (int p = 0; p < 4; ++p) c2[i][p] = make_float2(0.f, 0.f);

    for (int kt = 0; kt < K; kt += 16) {
#pragma unroll
        for (int u = 0; u < 2; ++u) {
            int s   = tid + u * 256;
            int row = s >> 2;
            int c4  = s & 3;
            float4 av = *(const float4*)(A + (size_t)(m0 + row) * K + kt + c4 * 4);
            As[(c4 * 4 + 0) * 132 + row] = av.x;
            As[(c4 * 4 + 1) * 132 + row] = av.y;
            As[(c4 * 4 + 2) * 132 + row] = av.z;
            As[(c4 * 4 + 3) * 132 + row] = av.w;
            float4 bv = *(const float4*)(W + (size_t)(n0 + row) * K + kt + c4 * 4);
            Bs[(c4 * 4 + 0) * 132 + row] = bv.x;
            Bs[(c4 * 4 + 1) * 132 + row] = bv.y;
            Bs[(c4 * 4 + 2) * 132 + row] = bv.z;
            Bs[(c4 * 4 + 3) * 132 + row] = bv.w;
        }
        __syncthreads();

#pragma unroll
        for (int kb = 0; kb < 16; ++kb) {
            float4 a0 = *(const float4*)(As + kb * 132 + tm * 8);
            float4 a1 = *(const float4*)(As + kb * 132 + tm * 8 + 4);
            float4 b0 = *(const float4*)(Bs + kb * 132 + tn * 8);
            float4 b1 = *(const float4*)(Bs + kb * 132 + tn * 8 + 4);
            float av[8] = {a0.x, a0.y, a0.z, a0.w, a1.x, a1.y, a1.z, a1.w};
            float2 bp[4] = {make_float2(b0.x, b0.y), make_float2(b0.z, b0.w),
                            make_float2(b1.x, b1.y), make_float2(b1.z, b1.w)};
#pragma unroll
            for (int i = 0; i < 8; ++i) {
                float2 as = make_float2(av[i], av[i]);
#pragma unroll
                for (int p = 0; p < 4; ++p) c2[i][p] = ffma2(as, bp[p], c2[i][p]);
            }
        }
        __syncthreads();
    }

    const float4 bb0 = *(const float4*)(bias + n0 + tn * 8);
    const float4 bb1 = *(const float4*)(bias + n0 + tn * 8 + 4);
#pragma unroll
    for (int i = 0; i < 8; ++i) {
        int m = m0 + tm * 8 + i;
        float4 o0 = make_float4(c2[i][0].x + bb0.x, c2[i][0].y + bb0.y,
                                c2[i][1].x + bb0.z, c2[i][1].y + bb0.w);
        float4 o1 = make_float4(c2[i][2].x + bb1.x, c2[i][2].y + bb1.y,
                                c2[i][3].x + bb1.z, c2[i][3].y + bb1.w);
        float* dst = out + (size_t)m * GATES3 + n0 + tn * 8;
        *(float4*)(dst)     = o0;
        *(float4*)(dst + 4) = o1;
    }
}

// ---------------- persistent GRU recurrence (R5 + fused fine-grained polling) ----------
// 128 blocks = 16 col-groups x 8 batch-groups; 256 threads = 32 cols x 8 batches.
// Each thread: 1 col, 3 gates, 1 batch, full k=512, FFMA2 packed along k.
// Per-step wait is fused into staging: each thread polls ONLY the producer block
// of its own k-range, then immediately loads that block's h slice.
__global__ void __launch_bounds__(NT_REC, 1) gru_rec_kernel(
    const float* __restrict__ xg, const float* __restrict__ Whh,
    const float* __restrict__ bhh, float* __restrict__ y,
    float* __restrict__ hn_out)
{
    extern __shared__ float smem[];
    float* Ws = smem;                 // 96 rows (g*32+col) x 516 floats
    float* hs = smem + 96 * WR;       // 8 rows (batch) x 516 floats

    const int tid  = threadIdx.x;
    const int bid  = blockIdx.x;
    const int cg   = bid & 15;
    const int grp  = bid >> 4;
    const int j0   = cg * 32;
    const int b0   = grp * 8;
    const int col  = tid >> 3;       // 0..31
    const int bsub = tid & 7;        // 0..7
    const int b    = b0 + bsub;
    const int j    = j0 + col;

    // one-time: W_hh slice (96 rows x 512, coalesced gmem read)
    for (int idx = tid; idx < 96 * 512; idx += NT_REC) {
        int row = idx >> 9;
        int k   = idx & 511;
        int g   = row >> 5;
        int c   = row & 31;
        Ws[row * WR + k] = Whh[(size_t)(g * HID + j0 + c) * HID + k];
    }
    for (int idx = tid; idx < 8 * WR; idx += NT_REC) hs[idx] = 0.f;

    const float bhr = bhh[j];
    const float bhz = bhh[HID + j];
    const float bhn = bhh[2 * HID + j];

    const float* wr = Ws + col * WR;
    const float* wz = Ws + (32 + col) * WR;
    const float* wn = Ws + (64 + col) * WR;
    const float* hb = hs + bsub * WR;

    // staging geometry: thread stages k4 = (tid&127)*4 for batches (tid>>7)+{0,2,4,6}... 
    // actually k-range fixed, batch varies with i; producer col-block = k4/32.
    const int skq  = tid & 127;              // k-quarter index (float4 granularity)
    const int sk4  = skq * 4;                // k offset
    const int scb  = skq >> 3;               // producer col-block (k4/32)
    const int sbh  = tid >> 7;               // 0..1
    const unsigned* myflag = &g_flags[grp * 16 + scb];

    const size_t xofs = (size_t)b * GATES3 + j;
    float xr = xg[xofs];
    float xz = xg[xofs + HID];
    float xn = xg[xofs + 2 * HID];

    float hp = 0.f;   // own h, in regs
    __syncthreads();

    for (int t = 0; t < T_STEPS; ++t) {
        if (t > 0) {
            // fine-grained: poll ONLY this thread's producer block, then load its slice
            unsigned v;
            do {
                asm volatile("ld.acquire.gpu.global.u32 %0, [%1];" : "=r"(v) : "l"(myflag));
            } while (v < (unsigned)t);
            const float* hsrc = g_hx + (size_t)(t & 1) * BATCH * HID;
#pragma unroll
            for (int i = 0; i < 4; ++i) {
                int bb = sbh * 4 + i;   // 4 batches per thread (2 halves x 4)
                float4 hv = __ldcg((const float4*)(hsrc + (size_t)(b0 + bb) * HID + sk4));
                *(float4*)(hs + bb * WR + sk4) = hv;
            }
            __syncthreads();
        }

        // prefetch next step's xg early: LDG latency hides under the FMA loop
        float nxr = 0.f, nxz = 0.f, nxn = 0.f;
        if (t + 1 < T_STEPS) {
            const float* xp = xg + (size_t)(t + 1) * BATCH * GATES3 + xofs;
            nxr = __ldg(xp);
            nxz = __ldg(xp + HID);
            nxn = __ldg(xp + 2 * HID);
        }

        // full-k dot, FFMA2 packed along k: 3 gates x 1 col x 1 batch
        float2 r0 = {0, 0}, r1 = {0, 0};
        float2 z0 = {0, 0}, z1 = {0, 0};
        float2 n0 = {0, 0}, n1 = {0, 0};
#pragma unroll 8
        for (int k = 0; k < HID; k += 8) {
            float4 h0 = *(const float4*)(hb + k);
            float4 h1 = *(const float4*)(hb + k + 4);
            float4 a0 = *(const float4*)(wr + k);
            float4 a1 = *(const float4*)(wr + k + 4);
            float4 c0 = *(const float4*)(wz + k);
            float4 c1 = *(const float4*)(wz + k + 4);
            float4 d0 = *(const float4*)(wn + k);
            float4 d1 = *(const float4*)(wn + k + 4);
            r0 = ffma2(make_float2(a0.x, a0.y), make_float2(h0.x, h0.y), r0);
            r1 = ffma2(make_float2(a0.z, a0.w), make_float2(h0.z, h0.w), r1);
            z0 = ffma2(make_float2(c0.x, c0.y), make_float2(h0.x, h0.y), z0);
            z1 = ffma2(make_float2(c0.z, c0.w), make_float2(h0.z, h0.w), z1);
            n0 = ffma2(make_float2(d0.x, d0.y), make_float2(h0.x, h0.y), n0);
            n1 = ffma2(make_float2(d0.z, d0.w), make_float2(h0.z, h0.w), n1);
            r0 = ffma2(make_float2(a1.x, a1.y), make_float2(h1.x, h1.y), r0);
            r1 = ffma2(make_float2(a1.z, a1.w), make_float2(h1.z, h1.w), r1);
            z0 = ffma2(make_float2(c1.x, c1.y), make_float2(h1.x, h1.y), z0);
            z1 = ffma2(make_float2(c1.z, c1.w), make_float2(h1.z, h1.w), z1);
            n0 = ffma2(make_float2(d1.x, d1.y), make_float2(h1.x, h1.y), n0);
            n1 = ffma2(make_float2(d1.z, d1.w), make_float2(h1.z, h1.w), n1);
        }
        float hr = r0.x + r0.y + r1.x + r1.y + bhr;
        float hz = z0.x + z0.y + z1.x + z1.y + bhz;
        float hn = n0.x + n0.y + n1.x + n1.y + bhn;

        // finalize (fast approx transcendentals)
        float rg = fast_sigmoid(xr + hr);
        float zg = fast_sigmoid(xz + hz);
        float ng = fast_tanh(xn + rg * hn);
        hp = (1.f - zg) * ng + zg * hp;

        // publish h FIRST (critical path), then flag
        g_hx[(size_t)((t + 1) & 1) * BATCH * HID + (size_t)b * HID + j] = hp;
        __syncthreads();
        if (tid == 0 && t < T_STEPS - 1) {
            __threadfence();
            asm volatile("st.global.cg.u32 [%0], %1;"
                         :: "l"(&g_flags[bid]), "r"((unsigned)(t + 1)) : "memory");
        }

        // off critical path: y store, hn store
        y[((size_t)t * BATCH + b) * HID + j] = hp;
        if (t == T_STEPS - 1) hn_out[(size_t)b * HID + j] = hp;

        xr = nxr; xz = nxz; xn = nxn;
    }

    // end-of-launch: group gen-barrier (replay-safe), reset own flag
    __syncthreads();
    if (tid == 0) {
        unsigned gen = g_end_gen[grp];
        __threadfence();
        if (atomicAdd(&g_end_cnt[grp], 1u) == 15u) {
            g_end_cnt[grp] = 0u;
            __threadfence();
            g_end_gen[grp] = gen + 1u;
        } else {
            while (g_end_gen[grp] == gen) { __nanosleep(32); }
        }
        g_flags[bid] = 0u;
        __threadfence();
    }
}

// ---------------- launch ----------------
extern "C" void kernel_launch(void* const* d_in, const int* in_sizes, int n_in,
                              void* d_out, int out_size) {
    const float* x    = (const float*)d_in[0];
    const float* Wih0 = (const float*)d_in[1];
    const float* Whh0 = (const float*)d_in[2];
    const float* bih0 = (const float*)d_in[3];
    const float* bhh0 = (const float*)d_in[4];
    const float* Wih1 = (const float*)d_in[5];
    const float* Whh1 = (const float*)d_in[6];
    const float* bih1 = (const float*)d_in[7];
    const float* bhh1 = (const float*)d_in[8];

    float* out = (float*)d_out;
    float* y1  = out;
    float* hn0 = out + (size_t)T_STEPS * BATCH * HID;
    float* hn1 = hn0 + BATCH * HID;

    float *xg, *y0;
    cudaGetSymbolAddress((void**)&xg, g_xg);
    cudaGetSymbolAddress((void**)&y0, g_y0);

    const int rec_smem = (96 * WR + 8 * WR) * 4;  // 214,656 B
    cudaFuncSetAttribute(gru_rec_kernel, cudaFuncAttributeMaxDynamicSharedMemorySize, rec_smem);

    dim3 ggrid(12, 256);

    gemm_bias_kernel<<<ggrid, 256>>>(x, Wih0, bih0, xg, 256);
    gru_rec_kernel<<<NB_REC, NT_REC, rec_smem>>>(xg, Whh0, bhh0, y0, hn0);
    gemm_bias_kernel<<<ggrid, 256>>>(y0, Wih1, bih1, xg, 512);
    gru_rec_kernel<<<NB_REC, NT_REC, rec_smem>>>(xg, Whh1, bhh1, y1, hn1);
}

// round 9
// speedup vs baseline: 1.5056x; 1.5056x over previous
#include <cuda_runtime.h>

#define T_STEPS 512
#define BATCH   64
#define HID     512
#define GATES3  1536
#define NB_REC  128
#define NT_REC  256
#define WR      516   // float stride for smem rows (padded: conflict-free)

// ---------------- scratch (static device allocations; no cudaMalloc) ----------------
__device__ float g_xg[(size_t)T_STEPS * BATCH * GATES3]; // precomputed input gates
__device__ float g_y0[(size_t)T_STEPS * BATCH * HID];    // layer-0 output
__device__ float g_hx[2 * BATCH * HID];                  // ping-pong h exchange [parity][b][j]
__device__ unsigned g_flags[NB_REC];                     // per-block step flags
__device__ unsigned g_end_cnt[8];
__device__ volatile unsigned g_end_gen[8];

// ---------------- packed fp32x2 FMA (Blackwell FFMA2) ----------------
__device__ __forceinline__ float2 ffma2(float2 a, float2 b, float2 c) {
    float2 d;
    asm("fma.rn.f32x2 %0, %1, %2, %3;"
        : "=l"(reinterpret_cast<unsigned long long&>(d))
        : "l"(reinterpret_cast<unsigned long long&>(a)),
          "l"(reinterpret_cast<unsigned long long&>(b)),
          "l"(reinterpret_cast<unsigned long long&>(c)));
    return d;
}

__device__ __forceinline__ float fast_sigmoid(float x) {
    return __fdividef(1.f, 1.f + __expf(-x));
}
__device__ __forceinline__ float fast_tanh(float x) {
    float r;
    asm("tanh.approx.f32 %0, %1;" : "=f"(r) : "f"(x));
    return r;
}

// ---------------- GEMM: out[M,N] = A[M,K] * W[N,K]^T + bias (R2 version, known-good) ----
__global__ void __launch_bounds__(256) gemm_bias_kernel(
    const float* __restrict__ A, const float* __restrict__ W,
    const float* __restrict__ bias, float* __restrict__ out, int K)
{
    __shared__ float As[16 * 132];
    __shared__ float Bs[16 * 132];

    const int tid = threadIdx.x;
    const int m0 = blockIdx.y * 128;
    const int n0 = blockIdx.x * 128;
    const int tm = tid >> 4;
    const int tn = tid & 15;

    float2 c2[8][4];
#pragma unroll
    for (int i = 0; i < 8; ++i)
#pragma unroll
        for (int p = 0; p < 4; ++p) c2[i][p] = make_float2(0.f, 0.f);

    for (int kt = 0; kt < K; kt += 16) {
#pragma unroll
        for (int u = 0; u < 2; ++u) {
            int s   = tid + u * 256;
            int row = s >> 2;
            int c4  = s & 3;
            float4 av = *(const float4*)(A + (size_t)(m0 + row) * K + kt + c4 * 4);
            As[(c4 * 4 + 0) * 132 + row] = av.x;
            As[(c4 * 4 + 1) * 132 + row] = av.y;
            As[(c4 * 4 + 2) * 132 + row] = av.z;
            As[(c4 * 4 + 3) * 132 + row] = av.w;
            float4 bv = *(const float4*)(W + (size_t)(n0 + row) * K + kt + c4 * 4);
            Bs[(c4 * 4 + 0) * 132 + row] = bv.x;
            Bs[(c4 * 4 + 1) * 132 + row] = bv.y;
            Bs[(c4 * 4 + 2) * 132 + row] = bv.z;
            Bs[(c4 * 4 + 3) * 132 + row] = bv.w;
        }
        __syncthreads();

#pragma unroll
        for (int kb = 0; kb < 16; ++kb) {
            float4 a0 = *(const float4*)(As + kb * 132 + tm * 8);
            float4 a1 = *(const float4*)(As + kb * 132 + tm * 8 + 4);
            float4 b0 = *(const float4*)(Bs + kb * 132 + tn * 8);
            float4 b1 = *(const float4*)(Bs + kb * 132 + tn * 8 + 4);
            float av[8] = {a0.x, a0.y, a0.z, a0.w, a1.x, a1.y, a1.z, a1.w};
            float2 bp[4] = {make_float2(b0.x, b0.y), make_float2(b0.z, b0.w),
                            make_float2(b1.x, b1.y), make_float2(b1.z, b1.w)};
#pragma unroll
            for (int i = 0; i < 8; ++i) {
                float2 as = make_float2(av[i], av[i]);
#pragma unroll
                for (int p = 0; p < 4; ++p) c2[i][p] = ffma2(as, bp[p], c2[i][p]);
            }
        }
        __syncthreads();
    }

    const float4 bb0 = *(const float4*)(bias + n0 + tn * 8);
    const float4 bb1 = *(const float4*)(bias + n0 + tn * 8 + 4);
#pragma unroll
    for (int i = 0; i < 8; ++i) {
        int m = m0 + tm * 8 + i;
        float4 o0 = make_float4(c2[i][0].x + bb0.x, c2[i][0].y + bb0.y,
                                c2[i][1].x + bb0.z, c2[i][1].y + bb0.w);
        float4 o1 = make_float4(c2[i][2].x + bb1.x, c2[i][2].y + bb1.y,
                                c2[i][3].x + bb1.z, c2[i][3].y + bb1.w);
        float* dst = out + (size_t)m * GATES3 + n0 + tn * 8;
        *(float4*)(dst)     = o0;
        *(float4*)(dst + 4) = o1;
    }
}

// ---------------- persistent GRU recurrence (R5 champion + surgical cuts) ----------
// 128 blocks = 16 col-groups x 8 batch-groups; 256 threads = 32 cols x 8 batches.
// Each thread: 1 col, 3 gates, 1 batch, full k=512, FFMA2 packed along k.
// Own 32-col h slice written directly to smem (no global round trip for it);
// group barrier = 15-flag poll by tid<16 threads (own flag skipped).
__global__ void __launch_bounds__(NT_REC, 1) gru_rec_kernel(
    const float* __restrict__ xg, const float* __restrict__ Whh,
    const float* __restrict__ bhh, float* __restrict__ y,
    float* __restrict__ hn_out)
{
    extern __shared__ float smem[];
    float* Ws = smem;                 // 96 rows (g*32+col) x 516 floats
    float* hs = smem + 96 * WR;       // 8 rows (batch) x 516 floats

    const int tid  = threadIdx.x;
    const int bid  = blockIdx.x;
    const int cg   = bid & 15;
    const int grp  = bid >> 4;
    const int j0   = cg * 32;
    const int b0   = grp * 8;
    const int col  = tid >> 3;       // 0..31
    const int bsub = tid & 7;        // 0..7
    const int b    = b0 + bsub;
    const int j    = j0 + col;

    // one-time: W_hh slice (96 rows x 512, coalesced gmem read)
    for (int idx = tid; idx < 96 * 512; idx += NT_REC) {
        int row = idx >> 9;
        int k   = idx & 511;
        int g   = row >> 5;
        int c   = row & 31;
        Ws[row * WR + k] = Whh[(size_t)(g * HID + j0 + c) * HID + k];
    }
    for (int idx = tid; idx < 8 * WR; idx += NT_REC) hs[idx] = 0.f;

    const float bhr = bhh[j];
    const float bhz = bhh[HID + j];
    const float bhn = bhh[2 * HID + j];

    const float* wr = Ws + col * WR;
    const float* wz = Ws + (32 + col) * WR;
    const float* wn = Ws + (64 + col) * WR;
    const float* hb = hs + bsub * WR;

    const size_t xofs = (size_t)b * GATES3 + j;
    float xr = xg[xofs];
    float xz = xg[xofs + HID];
    float xn = xg[xofs + 2 * HID];

    // staging geometry (own col-block skipped — written directly at finalize)
    const int skq = tid >> 1;               // 0..127 k-quarter
    const int sk4 = skq * 4;
    const int scb = skq >> 3;               // producer col-block of this k-range
    const int sbh = tid & 1;                // batch half (4 batches each)
    const bool stage_mine = (scb != cg);

    float hp = 0.f;   // own h, in regs
    __syncthreads();

    for (int t = 0; t < T_STEPS; ++t) {
        if (t > 0) {
            // group barrier: 15 remote flags (own block's slice already in smem)
            if (tid < 16 && tid != cg) {
                const unsigned* fp = &g_flags[grp * 16 + tid];
                unsigned v;
                do {
                    asm volatile("ld.acquire.gpu.global.u32 %0, [%1];" : "=r"(v) : "l"(fp));
                } while (v < (unsigned)t);
            }
            __syncthreads();
            // stage remote h (15/16 of 16 KB) for this group's 8 batches
            if (stage_mine) {
                const float* hsrc = g_hx + (size_t)(t & 1) * BATCH * HID;
#pragma unroll
                for (int i = 0; i < 4; ++i) {
                    int bb = sbh * 4 + i;
                    float4 hv = __ldcg((const float4*)(hsrc + (size_t)(b0 + bb) * HID + sk4));
                    *(float4*)(hs + bb * WR + sk4) = hv;
                }
            }
            __syncthreads();
        }

        // prefetch next step's xg early: LDG latency hides under the FMA loop
        float nxr = 0.f, nxz = 0.f, nxn = 0.f;
        if (t + 1 < T_STEPS) {
            const float* xp = xg + (size_t)(t + 1) * BATCH * GATES3 + xofs;
            nxr = __ldg(xp);
            nxz = __ldg(xp + HID);
            nxn = __ldg(xp + 2 * HID);
        }

        // full-k dot, FFMA2 packed along k: 3 gates x 1 col x 1 batch
        float2 r0 = {0, 0}, r1 = {0, 0};
        float2 z0 = {0, 0}, z1 = {0, 0};
        float2 n0 = {0, 0}, n1 = {0, 0};
#pragma unroll 8
        for (int k = 0; k < HID; k += 8) {
            float4 h0 = *(const float4*)(hb + k);
            float4 h1 = *(const float4*)(hb + k + 4);
            float4 a0 = *(const float4*)(wr + k);
            float4 a1 = *(const float4*)(wr + k + 4);
            float4 c0 = *(const float4*)(wz + k);
            float4 c1 = *(const float4*)(wz + k + 4);
            float4 d0 = *(const float4*)(wn + k);
            float4 d1 = *(const float4*)(wn + k + 4);
            r0 = ffma2(make_float2(a0.x, a0.y), make_float2(h0.x, h0.y), r0);
            r1 = ffma2(make_float2(a0.z, a0.w), make_float2(h0.z, h0.w), r1);
            z0 = ffma2(make_float2(c0.x, c0.y), make_float2(h0.x, h0.y), z0);
            z1 = ffma2(make_float2(c0.z, c0.w), make_float2(h0.z, h0.w), z1);
            n0 = ffma2(make_float2(d0.x, d0.y), make_float2(h0.x, h0.y), n0);
            n1 = ffma2(make_float2(d0.z, d0.w), make_float2(h0.z, h0.w), n1);
            r0 = ffma2(make_float2(a1.x, a1.y), make_float2(h1.x, h1.y), r0);
            r1 = ffma2(make_float2(a1.z, a1.w), make_float2(h1.z, h1.w), r1);
            z0 = ffma2(make_float2(c1.x, c1.y), make_float2(h1.x, h1.y), z0);
            z1 = ffma2(make_float2(c1.z, c1.w), make_float2(h1.z, h1.w), z1);
            n0 = ffma2(make_float2(d1.x, d1.y), make_float2(h1.x, h1.y), n0);
            n1 = ffma2(make_float2(d1.z, d1.w), make_float2(h1.z, h1.w), n1);
        }
        float hr = r0.x + r0.y + r1.x + r1.y + bhr;
        float hz = z0.x + z0.y + z1.x + z1.y + bhz;
        float hn = n0.x + n0.y + n1.x + n1.y + bhn;

        // finalize (fast approx transcendentals; rel_err ~4e-6, OK vs 1e-3)
        float rg = fast_sigmoid(xr + hr);
        float zg = fast_sigmoid(xz + hz);
        float ng = fast_tanh(xn + rg * hn);
        hp = (1.f - zg) * ng + zg * hp;

        // publish h to L2 FIRST (critical path for remote blocks), then flag
        {
            float* hdst = g_hx + (size_t)((t + 1) & 1) * BATCH * HID + (size_t)b * HID + j;
            asm volatile("st.global.cg.f32 [%0], %1;" :: "l"(hdst), "f"(hp) : "memory");
        }
        __syncthreads();
        if (tid == 0 && t < T_STEPS - 1) {
            __threadfence();
            asm volatile("st.global.cg.u32 [%0], %1;"
                         :: "l"(&g_flags[bid]), "r"((unsigned)(t + 1)) : "memory");
        }

        // own-slice shortcut: write own h directly into smem for next step
        // (safe here: post-sync, nobody reads hs until after next staging sync)
        hs[bsub * WR + j0 + col] = hp;

        // off critical path: y store, hn store
        y[((size_t)t * BATCH + b) * HID + j] = hp;
        if (t == T_STEPS - 1) hn_out[(size_t)b * HID + j] = hp;

        xr = nxr; xz = nxz; xn = nxn;
    }

    // end-of-launch: group gen-barrier (replay-safe), reset own flag
    __syncthreads();
    if (tid == 0) {
        unsigned gen = g_end_gen[grp];
        __threadfence();
        if (atomicAdd(&g_end_cnt[grp], 1u) == 15u) {
            g_end_cnt[grp] = 0u;
            __threadfence();
            g_end_gen[grp] = gen + 1u;
        } else {
            while (g_end_gen[grp] == gen) { __nanosleep(32); }
        }
        g_flags[bid] = 0u;
        __threadfence();
    }
}

// ---------------- launch ----------------
extern "C" void kernel_launch(void* const* d_in, const int* in_sizes, int n_in,
                              void* d_out, int out_size) {
    const float* x    = (const float*)d_in[0];
    const float* Wih0 = (const float*)d_in[1];
    const float* Whh0 = (const float*)d_in[2];
    const float* bih0 = (const float*)d_in[3];
    const float* bhh0 = (const float*)d_in[4];
    const float* Wih1 = (const float*)d_in[5];
    const float* Whh1 = (const float*)d_in[6];
    const float* bih1 = (const float*)d_in[7];
    const float* bhh1 = (const float*)d_in[8];

    float* out = (float*)d_out;
    float* y1  = out;
    float* hn0 = out + (size_t)T_STEPS * BATCH * HID;
    float* hn1 = hn0 + BATCH * HID;

    float *xg, *y0;
    cudaGetSymbolAddress((void**)&xg, g_xg);
    cudaGetSymbolAddress((void**)&y0, g_y0);

    const int rec_smem = (96 * WR + 8 * WR) * 4;  // 214,656 B
    cudaFuncSetAttribute(gru_rec_kernel, cudaFuncAttributeMaxDynamicSharedMemorySize, rec_smem);

    dim3 ggrid(12, 256);

    gemm_bias_kernel<<<ggrid, 256>>>(x, Wih0, bih0, xg, 256);
    gru_rec_kernel<<<NB_REC, NT_REC, rec_smem>>>(xg, Whh0, bhh0, y0, hn0);
    gemm_bias_kernel<<<ggrid, 256>>>(y0, Wih1, bih1, xg, 512);
    gru_rec_kernel<<<NB_REC, NT_REC, rec_smem>>>(xg, Whh1, bhh1, y1, hn1);
}